// round 1
// baseline (speedup 1.0000x reference)
#include <cuda_runtime.h>

#define N_ENT 200000
#define EE    4000000
#define R_SR  1000
#define R_TG  1200
#define DD    128

// d_out layout (floats):
// [0, EE)                       sr edge vals
// [EE, EE+N_ENT)                sr diag vals
// [EE+N_ENT, 2EE+N_ENT)         tg edge vals
// [2EE+N_ENT, 2EE+2N_ENT)       tg diag vals
// [OFF_RW, OFF_RW+R_SR)         rw_sr
// [OFF_RW+R_SR, +R_TG)          rw_tg
#define OFF_RW (2*(EE + N_ENT))

__device__ float g_deg_sr[N_ENT];
__device__ float g_deg_tg[N_ENT];
__device__ float g_an[R_SR * DD];
__device__ float g_bn[R_TG * DD];

__device__ __forceinline__ float negInf() { return __int_as_float(0xff800000); }

// float atomic max valid for mixed signs: non-negative floats order like ints,
// negative floats order inversely like unsigned ints.
__device__ __forceinline__ void atomicMaxFloat(float* addr, float val) {
    if (val >= 0.f) atomicMax((int*)addr, __float_as_int(val));
    else            atomicMin((unsigned int*)addr, __float_as_uint(val));
}

// ---------------------------------------------------------------------------
// init: deg = 1 (identity contribution), rw_sr = -inf, rw_tg = 0 (zero-pad rows)
__global__ __launch_bounds__(256) void k_init(float* out) {
    int i = blockIdx.x * blockDim.x + threadIdx.x;
    if (i < N_ENT) { g_deg_sr[i] = 1.f; g_deg_tg[i] = 1.f; }
    if (i < R_SR)  out[OFF_RW + i] = negInf();
    if (i < R_TG)  out[OFF_RW + R_SR + i] = 0.f;
}

// ---------------------------------------------------------------------------
// normalize relation embeddings: one warp per row
__global__ __launch_bounds__(256) void k_normrel(const float* __restrict__ A,
                                                 const float* __restrict__ B) {
    int warp = (blockIdx.x * blockDim.x + threadIdx.x) >> 5;
    int lane = threadIdx.x & 31;
    const float* src; float* dst; int row;
    if (warp < R_SR)              { src = A; dst = g_an; row = warp; }
    else if (warp < R_SR + R_TG)  { src = B; dst = g_bn; row = warp - R_SR; }
    else return;
    float v[4]; float s = 0.f;
#pragma unroll
    for (int j = 0; j < 4; j++) { v[j] = src[row * DD + lane + 32 * j]; s += v[j] * v[j]; }
#pragma unroll
    for (int o = 16; o; o >>= 1) s += __shfl_xor_sync(0xffffffffu, s, o);
    float sc = rsqrtf(s + 1e-8f);
#pragma unroll
    for (int j = 0; j < 4; j++) dst[row * DD + lane + 32 * j] = v[j] * sc;
}

// ---------------------------------------------------------------------------
// vals = conf*imp*pca, staged into d_out; atomicAdd into deg[head]. Both sides.
__global__ __launch_bounds__(256) void k_vals(
    const float4* __restrict__ c_sr, const float4* __restrict__ i_sr,
    const float4* __restrict__ p_sr, const int4*  __restrict__ h_sr,
    const float4* __restrict__ c_tg, const float4* __restrict__ i_tg,
    const float4* __restrict__ p_tg, const int4*  __restrict__ h_tg,
    float* __restrict__ out) {
    int tid = blockIdx.x * blockDim.x + threadIdx.x;
    const int Q = EE / 4;
    if (tid < Q) {
        float4 c = c_sr[tid], m = i_sr[tid], p = p_sr[tid];
        int4 h = h_sr[tid];
        float4 v = make_float4(c.x * m.x * p.x, c.y * m.y * p.y,
                               c.z * m.z * p.z, c.w * m.w * p.w);
        ((float4*)out)[tid] = v;
        atomicAdd(&g_deg_sr[h.x], v.x); atomicAdd(&g_deg_sr[h.y], v.y);
        atomicAdd(&g_deg_sr[h.z], v.z); atomicAdd(&g_deg_sr[h.w], v.w);
    } else if (tid < 2 * Q) {
        int t = tid - Q;
        float4 c = c_tg[t], m = i_tg[t], p = p_tg[t];
        int4 h = h_tg[t];
        float4 v = make_float4(c.x * m.x * p.x, c.y * m.y * p.y,
                               c.z * m.z * p.z, c.w * m.w * p.w);
        ((float4*)(out + EE + N_ENT))[t] = v;
        atomicAdd(&g_deg_tg[h.x], v.x); atomicAdd(&g_deg_tg[h.y], v.y);
        atomicAdd(&g_deg_tg[h.z], v.z); atomicAdd(&g_deg_tg[h.w], v.w);
    }
}

// ---------------------------------------------------------------------------
// deg -> rsqrt(deg) in place; also emit diag output = dis^2. Both sides.
__global__ __launch_bounds__(256) void k_rsqrt_diag(float* __restrict__ out) {
    int tid = blockIdx.x * blockDim.x + threadIdx.x;
    const int Q = N_ENT / 4;
    if (tid < Q) {
        float4 d = ((float4*)g_deg_sr)[tid];
        float4 r = make_float4(rsqrtf(d.x), rsqrtf(d.y), rsqrtf(d.z), rsqrtf(d.w));
        ((float4*)g_deg_sr)[tid] = r;
        ((float4*)(out + EE))[tid] = make_float4(r.x * r.x, r.y * r.y, r.z * r.z, r.w * r.w);
    } else if (tid < 2 * Q) {
        int t = tid - Q;
        float4 d = ((float4*)g_deg_tg)[t];
        float4 r = make_float4(rsqrtf(d.x), rsqrtf(d.y), rsqrtf(d.z), rsqrtf(d.w));
        ((float4*)g_deg_tg)[t] = r;
        ((float4*)(out + 2 * EE + N_ENT))[t] = make_float4(r.x * r.x, r.y * r.y, r.z * r.z, r.w * r.w);
    }
}

// ---------------------------------------------------------------------------
// edge normalize: out_edge *= dis[head] * dis[tail]. Both sides.
__global__ __launch_bounds__(256) void k_norm(
    const int4* __restrict__ h_sr, const int4* __restrict__ t_sr,
    const int4* __restrict__ h_tg, const int4* __restrict__ t_tg,
    float* __restrict__ out) {
    int tid = blockIdx.x * blockDim.x + threadIdx.x;
    const int Q = EE / 4;
    if (tid < Q) {
        int4 h = h_sr[tid], t = t_sr[tid];
        float4 v = ((float4*)out)[tid];
        v.x *= g_deg_sr[h.x] * g_deg_sr[t.x];
        v.y *= g_deg_sr[h.y] * g_deg_sr[t.y];
        v.z *= g_deg_sr[h.z] * g_deg_sr[t.z];
        v.w *= g_deg_sr[h.w] * g_deg_sr[t.w];
        ((float4*)out)[tid] = v;
    } else if (tid < 2 * Q) {
        int id = tid - Q;
        int4 h = h_tg[id], t = t_tg[id];
        float4* base = (float4*)(out + EE + N_ENT);
        float4 v = base[id];
        v.x *= g_deg_tg[h.x] * g_deg_tg[t.x];
        v.y *= g_deg_tg[h.y] * g_deg_tg[t.y];
        v.z *= g_deg_tg[h.z] * g_deg_tg[t.z];
        v.w *= g_deg_tg[h.w] * g_deg_tg[t.w];
        base[id] = v;
    }
}

// ---------------------------------------------------------------------------
// cosine-sim 64x64 tile GEMM with row/col max-pool. A=g_an (1000xD), B=g_bn (1200xD)
__global__ __launch_bounds__(256) void k_relsim(float* __restrict__ rw_sr,
                                                float* __restrict__ rw_tg) {
    __shared__ float As[64][68];   // [k][m], stride 68 keeps 16B alignment
    __shared__ float Bs[64][68];   // [k][n]
    __shared__ float s_rmax[64], s_cmax[64];
    int tid = threadIdx.x;
    int tx = tid & 15, ty = tid >> 4;
    int iBase = blockIdx.x * 64, jBase = blockIdx.y * 64;
    float acc[4][4] = {};

    for (int kk = 0; kk < DD; kk += 64) {
        __syncthreads();
#pragma unroll
        for (int it = 0; it < 4; it++) {
            int f4 = tid + it * 256;          // 1024 float4s per tile
            int m = f4 & 63, kq = f4 >> 6;    // lanes span m -> conflict-free STS
            int gi = iBase + m;
            float4 a = (gi < R_SR)
                ? reinterpret_cast<const float4*>(g_an)[gi * (DD / 4) + (kk >> 2) + kq]
                : make_float4(0.f, 0.f, 0.f, 0.f);
            As[kq * 4 + 0][m] = a.x; As[kq * 4 + 1][m] = a.y;
            As[kq * 4 + 2][m] = a.z; As[kq * 4 + 3][m] = a.w;
            int gj = jBase + m;
            float4 b = (gj < R_TG)
                ? reinterpret_cast<const float4*>(g_bn)[gj * (DD / 4) + (kk >> 2) + kq]
                : make_float4(0.f, 0.f, 0.f, 0.f);
            Bs[kq * 4 + 0][m] = b.x; Bs[kq * 4 + 1][m] = b.y;
            Bs[kq * 4 + 2][m] = b.z; Bs[kq * 4 + 3][m] = b.w;
        }
        __syncthreads();
#pragma unroll 8
        for (int k = 0; k < 64; k++) {
            float4 a = *reinterpret_cast<float4*>(&As[k][ty * 4]);
            float4 b = *reinterpret_cast<float4*>(&Bs[k][tx * 4]);
            float av[4] = {a.x, a.y, a.z, a.w};
            float bv[4] = {b.x, b.y, b.z, b.w};
#pragma unroll
            for (int r = 0; r < 4; r++)
#pragma unroll
                for (int c = 0; c < 4; c++) acc[r][c] = fmaf(av[r], bv[c], acc[r][c]);
        }
    }

    if (tid < 64) { s_rmax[tid] = negInf(); s_cmax[tid] = negInf(); }
    __syncthreads();
#pragma unroll
    for (int r = 0; r < 4; r++) {
        float m = negInf();
#pragma unroll
        for (int c = 0; c < 4; c++)
            if (jBase + tx * 4 + c < R_TG) m = fmaxf(m, acc[r][c]);
        atomicMaxFloat(&s_rmax[ty * 4 + r], m);
    }
#pragma unroll
    for (int c = 0; c < 4; c++) {
        float m = negInf();
#pragma unroll
        for (int r = 0; r < 4; r++) m = fmaxf(m, acc[r][c]);
        atomicMaxFloat(&s_cmax[tx * 4 + c], m);
    }
    __syncthreads();
    if (tid < 64) {
        int gi = iBase + tid;
        if (gi < R_SR) atomicMaxFloat(&rw_sr[gi], s_rmax[tid]);
    } else if (tid < 128) {
        int c = tid - 64;
        int gj = jBase + c;
        if (gj < R_TG) atomicMaxFloat(&rw_tg[gj], s_cmax[c]);
    }
}

// ---------------------------------------------------------------------------
extern "C" void kernel_launch(void* const* d_in, const int* in_sizes, int n_in,
                              void* d_out, int out_size) {
    const float* rel_sr  = (const float*)d_in[0];
    const float* rel_tg  = (const float*)d_in[1];
    const float* conf_sr = (const float*)d_in[2];
    const float* imp_sr  = (const float*)d_in[3];
    const float* pca_sr  = (const float*)d_in[4];
    const float* conf_tg = (const float*)d_in[5];
    const float* imp_tg  = (const float*)d_in[6];
    const float* pca_tg  = (const float*)d_in[7];
    const int*   head_sr = (const int*)d_in[8];
    const int*   tail_sr = (const int*)d_in[9];
    const int*   head_tg = (const int*)d_in[11];
    const int*   tail_tg = (const int*)d_in[12];
    float* out = (float*)d_out;

    k_init<<<(N_ENT + 255) / 256, 256>>>(out);
    k_normrel<<<((R_SR + R_TG) * 32 + 255) / 256, 256>>>(rel_sr, rel_tg);
    k_vals<<<(2 * (EE / 4) + 255) / 256, 256>>>(
        (const float4*)conf_sr, (const float4*)imp_sr, (const float4*)pca_sr,
        (const int4*)head_sr,
        (const float4*)conf_tg, (const float4*)imp_tg, (const float4*)pca_tg,
        (const int4*)head_tg, out);
    k_rsqrt_diag<<<(2 * (N_ENT / 4) + 255) / 256, 256>>>(out);
    k_norm<<<(2 * (EE / 4) + 255) / 256, 256>>>(
        (const int4*)head_sr, (const int4*)tail_sr,
        (const int4*)head_tg, (const int4*)tail_tg, out);
    dim3 g((R_SR + 63) / 64, (R_TG + 63) / 64);
    k_relsim<<<g, 256>>>(out + OFF_RW, out + OFF_RW + R_SR);
}

// round 2
// speedup vs baseline: 1.1525x; 1.1525x over previous
#include <cuda_runtime.h>

#define N_ENT 200000
#define EE    4000000
#define R_SR  1000
#define R_TG  1200
#define DD    128

// d_out layout (floats):
// [0, EE)                 sr edge vals
// [EE, EE+N_ENT)          sr diag vals
// [EE+N_ENT, 2EE+N_ENT)   tg edge vals
// [2EE+N_ENT, 2EE+2N_ENT) tg diag vals
// [OFF_RW, +R_SR)         rw_sr
// [OFF_RW+R_SR, +R_TG)    rw_tg
#define OFF_RW (2*(EE + N_ENT))

#define QE (EE/4)            // float4 quads per edge list
#define RELTX 16             // (R_SR+63)/64
#define RELTY 19             // (R_TG+63)/64
#define REL_BLOCKS (RELTX*RELTY)          // 304
#define NORM_BLOCKS (((R_SR+R_TG)*32)/256)   // 275
#define DEGI_BLOCKS ((N_ENT/4 + 255)/256)    // 196
#define EDGE_BLOCKS ((2*QE + 255)/256)       // 7813

__device__ float g_deg_sr[N_ENT];
__device__ float g_deg_tg[N_ENT];
__device__ float g_an[R_SR * DD];
__device__ float g_bn[R_TG * DD];

__device__ __forceinline__ float negInf() { return __int_as_float(0xff800000); }

// float atomic max correct for mixed signs
__device__ __forceinline__ void atomicMaxFloat(float* addr, float val) {
    if (val >= 0.f) atomicMax((int*)addr, __float_as_int(val));
    else            atomicMin((unsigned int*)addr, __float_as_uint(val));
}

// ---------------------------------------------------------------------------
// prep: blocks [0,275): normalize rel embeddings (warp/row) + rw init
//       blocks [275,275+196): deg = 1 (identity contribution), float4
__global__ __launch_bounds__(256) void k_prep(const float* __restrict__ A,
                                              const float* __restrict__ B,
                                              float* __restrict__ out) {
    if (blockIdx.x < NORM_BLOCKS) {
        int gidx = blockIdx.x * 256 + threadIdx.x;
        if (gidx < R_SR) out[OFF_RW + gidx] = negInf();
        if (gidx < R_TG) out[OFF_RW + R_SR + gidx] = 0.f;
        int warp = gidx >> 5;
        int lane = threadIdx.x & 31;
        const float* src; float* dst; int row;
        if (warp < R_SR)             { src = A; dst = g_an; row = warp; }
        else if (warp < R_SR + R_TG) { src = B; dst = g_bn; row = warp - R_SR; }
        else return;
        float v[4]; float s = 0.f;
#pragma unroll
        for (int j = 0; j < 4; j++) { v[j] = src[row * DD + lane + 32 * j]; s += v[j] * v[j]; }
#pragma unroll
        for (int o = 16; o; o >>= 1) s += __shfl_xor_sync(0xffffffffu, s, o);
        float sc = rsqrtf(s + 1e-8f);
#pragma unroll
        for (int j = 0; j < 4; j++) dst[row * DD + lane + 32 * j] = v[j] * sc;
    } else {
        int j = (blockIdx.x - NORM_BLOCKS) * 256 + threadIdx.x;
        if (j < N_ENT / 4) {
            float4 one = make_float4(1.f, 1.f, 1.f, 1.f);
            ((float4*)g_deg_sr)[j] = one;
            ((float4*)g_deg_tg)[j] = one;
        }
    }
}

// ---------------------------------------------------------------------------
// main: blocks [0,304): relsim tiles (compute-bound, overlaps with vals)
//       blocks [304, 304+7813): vals = conf*imp*pca -> out staging + deg atomics
__global__ __launch_bounds__(256) void k_main(
    const float4* __restrict__ c_sr, const float4* __restrict__ i_sr,
    const float4* __restrict__ p_sr, const int4*  __restrict__ h_sr,
    const float4* __restrict__ c_tg, const float4* __restrict__ i_tg,
    const float4* __restrict__ p_tg, const int4*  __restrict__ h_tg,
    float* __restrict__ out) {
    if (blockIdx.x < REL_BLOCKS) {
        // ---- cosine-sim 64x64 tile with row/col max-pool ----
        __shared__ float As[64][68];
        __shared__ float Bs[64][68];
        __shared__ float s_rmax[64], s_cmax[64];
        float* rw_sr = out + OFF_RW;
        float* rw_tg = out + OFF_RW + R_SR;
        int tid = threadIdx.x;
        int tx = tid & 15, ty = tid >> 4;
        int bx = blockIdx.x % RELTX, by = blockIdx.x / RELTX;
        int iBase = bx * 64, jBase = by * 64;
        float acc[4][4] = {};
        for (int kk = 0; kk < DD; kk += 64) {
            __syncthreads();
#pragma unroll
            for (int it = 0; it < 4; it++) {
                int f4 = tid + it * 256;
                int m = f4 & 63, kq = f4 >> 6;
                int gi = iBase + m;
                float4 a = (gi < R_SR)
                    ? reinterpret_cast<const float4*>(g_an)[gi * (DD / 4) + (kk >> 2) + kq]
                    : make_float4(0.f, 0.f, 0.f, 0.f);
                As[kq * 4 + 0][m] = a.x; As[kq * 4 + 1][m] = a.y;
                As[kq * 4 + 2][m] = a.z; As[kq * 4 + 3][m] = a.w;
                int gj = jBase + m;
                float4 b = (gj < R_TG)
                    ? reinterpret_cast<const float4*>(g_bn)[gj * (DD / 4) + (kk >> 2) + kq]
                    : make_float4(0.f, 0.f, 0.f, 0.f);
                Bs[kq * 4 + 0][m] = b.x; Bs[kq * 4 + 1][m] = b.y;
                Bs[kq * 4 + 2][m] = b.z; Bs[kq * 4 + 3][m] = b.w;
            }
            __syncthreads();
#pragma unroll 8
            for (int k = 0; k < 64; k++) {
                float4 a = *reinterpret_cast<float4*>(&As[k][ty * 4]);
                float4 b = *reinterpret_cast<float4*>(&Bs[k][tx * 4]);
                float av[4] = {a.x, a.y, a.z, a.w};
                float bv[4] = {b.x, b.y, b.z, b.w};
#pragma unroll
                for (int r = 0; r < 4; r++)
#pragma unroll
                    for (int c = 0; c < 4; c++) acc[r][c] = fmaf(av[r], bv[c], acc[r][c]);
            }
        }
        if (tid < 64) { s_rmax[tid] = negInf(); s_cmax[tid] = negInf(); }
        __syncthreads();
#pragma unroll
        for (int r = 0; r < 4; r++) {
            float m = negInf();
#pragma unroll
            for (int c = 0; c < 4; c++)
                if (jBase + tx * 4 + c < R_TG) m = fmaxf(m, acc[r][c]);
            atomicMaxFloat(&s_rmax[ty * 4 + r], m);
        }
#pragma unroll
        for (int c = 0; c < 4; c++) {
            float m = negInf();
#pragma unroll
            for (int r = 0; r < 4; r++) m = fmaxf(m, acc[r][c]);
            atomicMaxFloat(&s_cmax[tx * 4 + c], m);
        }
        __syncthreads();
        if (tid < 64) {
            int gi = iBase + tid;
            if (gi < R_SR) atomicMaxFloat(&rw_sr[gi], s_rmax[tid]);
        } else if (tid < 128) {
            int c = tid - 64;
            int gj = jBase + c;
            if (gj < R_TG) atomicMaxFloat(&rw_tg[gj], s_cmax[c]);
        }
    } else {
        int tid = (blockIdx.x - REL_BLOCKS) * 256 + threadIdx.x;
        if (tid < QE) {
            float4 c = c_sr[tid], m = i_sr[tid], p = p_sr[tid];
            int4 h = h_sr[tid];
            float4 v = make_float4(c.x * m.x * p.x, c.y * m.y * p.y,
                                   c.z * m.z * p.z, c.w * m.w * p.w);
            ((float4*)out)[tid] = v;
            atomicAdd(&g_deg_sr[h.x], v.x); atomicAdd(&g_deg_sr[h.y], v.y);
            atomicAdd(&g_deg_sr[h.z], v.z); atomicAdd(&g_deg_sr[h.w], v.w);
        } else if (tid < 2 * QE) {
            int t = tid - QE;
            float4 c = c_tg[t], m = i_tg[t], p = p_tg[t];
            int4 h = h_tg[t];
            float4 v = make_float4(c.x * m.x * p.x, c.y * m.y * p.y,
                                   c.z * m.z * p.z, c.w * m.w * p.w);
            ((float4*)(out + EE + N_ENT))[t] = v;
            atomicAdd(&g_deg_tg[h.x], v.x); atomicAdd(&g_deg_tg[h.y], v.y);
            atomicAdd(&g_deg_tg[h.z], v.z); atomicAdd(&g_deg_tg[h.w], v.w);
        }
    }
}

// ---------------------------------------------------------------------------
// fin: blocks [0,7813): edge normalize with on-the-fly rsqrt of raw degrees
//      blocks [7813, 7813+196): diag = rsqrt(deg)^2 for both sides
__global__ __launch_bounds__(256) void k_fin(
    const int4* __restrict__ h_sr, const int4* __restrict__ t_sr,
    const int4* __restrict__ h_tg, const int4* __restrict__ t_tg,
    float* __restrict__ out) {
    if (blockIdx.x < EDGE_BLOCKS) {
        int tid = blockIdx.x * 256 + threadIdx.x;
        if (tid < QE) {
            int4 h = h_sr[tid], t = t_sr[tid];
            float4 v = ((float4*)out)[tid];
            v.x *= rsqrtf(g_deg_sr[h.x]) * rsqrtf(g_deg_sr[t.x]);
            v.y *= rsqrtf(g_deg_sr[h.y]) * rsqrtf(g_deg_sr[t.y]);
            v.z *= rsqrtf(g_deg_sr[h.z]) * rsqrtf(g_deg_sr[t.z]);
            v.w *= rsqrtf(g_deg_sr[h.w]) * rsqrtf(g_deg_sr[t.w]);
            ((float4*)out)[tid] = v;
        } else if (tid < 2 * QE) {
            int id = tid - QE;
            int4 h = h_tg[id], t = t_tg[id];
            float4* base = (float4*)(out + EE + N_ENT);
            float4 v = base[id];
            v.x *= rsqrtf(g_deg_tg[h.x]) * rsqrtf(g_deg_tg[t.x]);
            v.y *= rsqrtf(g_deg_tg[h.y]) * rsqrtf(g_deg_tg[t.y]);
            v.z *= rsqrtf(g_deg_tg[h.z]) * rsqrtf(g_deg_tg[t.z]);
            v.w *= rsqrtf(g_deg_tg[h.w]) * rsqrtf(g_deg_tg[t.w]);
            base[id] = v;
        }
    } else {
        int j = (blockIdx.x - EDGE_BLOCKS) * 256 + threadIdx.x;
        if (j < N_ENT / 4) {
            float4 d = ((float4*)g_deg_sr)[j];
            float4 r = make_float4(rsqrtf(d.x), rsqrtf(d.y), rsqrtf(d.z), rsqrtf(d.w));
            ((float4*)(out + EE))[j] =
                make_float4(r.x * r.x, r.y * r.y, r.z * r.z, r.w * r.w);
            float4 e = ((float4*)g_deg_tg)[j];
            float4 s = make_float4(rsqrtf(e.x), rsqrtf(e.y), rsqrtf(e.z), rsqrtf(e.w));
            ((float4*)(out + 2 * EE + N_ENT))[j] =
                make_float4(s.x * s.x, s.y * s.y, s.z * s.z, s.w * s.w);
        }
    }
}

// ---------------------------------------------------------------------------
extern "C" void kernel_launch(void* const* d_in, const int* in_sizes, int n_in,
                              void* d_out, int out_size) {
    const float* rel_sr  = (const float*)d_in[0];
    const float* rel_tg  = (const float*)d_in[1];
    const float* conf_sr = (const float*)d_in[2];
    const float* imp_sr  = (const float*)d_in[3];
    const float* pca_sr  = (const float*)d_in[4];
    const float* conf_tg = (const float*)d_in[5];
    const float* imp_tg  = (const float*)d_in[6];
    const float* pca_tg  = (const float*)d_in[7];
    const int*   head_sr = (const int*)d_in[8];
    const int*   tail_sr = (const int*)d_in[9];
    const int*   head_tg = (const int*)d_in[11];
    const int*   tail_tg = (const int*)d_in[12];
    float* out = (float*)d_out;

    k_prep<<<NORM_BLOCKS + DEGI_BLOCKS, 256>>>(rel_sr, rel_tg, out);
    k_main<<<REL_BLOCKS + EDGE_BLOCKS, 256>>>(
        (const float4*)conf_sr, (const float4*)imp_sr, (const float4*)pca_sr,
        (const int4*)head_sr,
        (const float4*)conf_tg, (const float4*)imp_tg, (const float4*)pca_tg,
        (const int4*)head_tg, out);
    k_fin<<<EDGE_BLOCKS + DEGI_BLOCKS, 256>>>(
        (const int4*)head_sr, (const int4*)tail_sr,
        (const int4*)head_tg, (const int4*)tail_tg, out);
}